// round 4
// baseline (speedup 1.0000x reference)
#include <cuda_runtime.h>

#define NN 50000
#define FD 128
#define EMAXED 1000000

// ---------------- device scratch (no allocations allowed) ----------------
__device__ float g_hs[NN * FD];      // (X@W) * dinv[row]
__device__ float g_a[NN * FD];       // layer-1 activations
__device__ int   g_deg[NN];
__device__ float g_dinv[NN];
__device__ int   g_rowptr[NN + 1];
__device__ int   g_cursor[NN];
__device__ int   g_col[EMAXED];      // CSR (by dst) source indices, self-loop first
__device__ int   g_bsum[256];
__device__ int   g_is64;

// ---------------- edge dtype detection (int64 vs int32) ----------------
// If edges are int64 with values < 50000, every odd 32-bit word is zero.
__global__ void detect_k(const int* __restrict__ ei) {
    int w = ei[2 * threadIdx.x + 1];
    int any = __syncthreads_or(w != 0);
    if (threadIdx.x == 0) g_is64 = (any == 0) ? 1 : 0;
}

__global__ void init_deg_k(int n) {
    int i = blockIdx.x * blockDim.x + threadIdx.x;
    if (i < n) g_deg[i] = 1;  // self-loop
}

__global__ void count_k(const void* __restrict__ ei, int E) {
    int e = blockIdx.x * blockDim.x + threadIdx.x;
    if (e >= E) return;
    int dst;
    if (g_is64) dst = (int)((const long long*)ei)[(long long)E + e];
    else        dst = ((const int*)ei)[E + e];
    atomicAdd(&g_deg[dst], 1);
}

// Exclusive scan of g_deg -> g_rowptr.  3 kernels: per-block scan, block-sum
// scan (serial, tiny), add offsets (+ dinv compute, + cursor init, + self slot).
__global__ void scan_local_k(int n) {
    int i = blockIdx.x * 1024 + threadIdx.x;
    int v = (i < n) ? g_deg[i] : 0;
    int lane = threadIdx.x & 31, wid = threadIdx.x >> 5;
    int x = v;
#pragma unroll
    for (int off = 1; off < 32; off <<= 1) {
        int t = __shfl_up_sync(0xffffffffu, x, off);
        if (lane >= off) x += t;
    }
    __shared__ int wsum[32];
    if (lane == 31) wsum[wid] = x;
    __syncthreads();
    if (wid == 0) {
        int y = wsum[lane];
#pragma unroll
        for (int off = 1; off < 32; off <<= 1) {
            int t = __shfl_up_sync(0xffffffffu, y, off);
            if (lane >= off) y += t;
        }
        wsum[lane] = y;
    }
    __syncthreads();
    int incl = x + (wid > 0 ? wsum[wid - 1] : 0);
    if (i < n) g_rowptr[i] = incl - v;           // local exclusive
    if (threadIdx.x == 1023) g_bsum[blockIdx.x] = incl;  // block total
}

__global__ void scan_block_k(int nbs, int n) {
    int run = 0;
    for (int b = 0; b < nbs; b++) { int t = g_bsum[b]; g_bsum[b] = run; run += t; }
    g_rowptr[n] = run;
}

__global__ void scan_add_k(int n) {
    int i = blockIdx.x * 1024 + threadIdx.x;
    if (i < n) {
        int p = g_rowptr[i] + g_bsum[blockIdx.x];
        g_rowptr[i] = p;
        g_col[p] = i;            // self-loop occupies the first slot (FIX)
        g_cursor[i] = p + 1;     // edges fill after it
        g_dinv[i] = rsqrtf((float)g_deg[i]);   // deg >= 1 always
    }
}

__global__ void fill_k(const void* __restrict__ ei, int E) {
    int e = blockIdx.x * blockDim.x + threadIdx.x;
    if (e >= E) return;
    int s, d;
    if (g_is64) {
        const long long* p = (const long long*)ei;
        s = (int)p[e];
        d = (int)p[(long long)E + e];
    } else {
        const int* p = (const int*)ei;
        s = p[e];
        d = p[E + e];
    }
    int pos = atomicAdd(&g_cursor[d], 1);
    g_col[pos] = s;
}

// ---------------- GEMM: out = (X @ W) * dinv[row], out = g_hs ----------------
// BM=64 rows per block, BN=128 (full width), BK=16.  256 threads,
// thread tile 8x4.  fp32 FFMA (half-rate on B300; f32x2 is the next lever).
__global__ void __launch_bounds__(256) gemm_k(const float* __restrict__ Xext,
                                              const float* __restrict__ W,
                                              int use_internal, int n) {
    const float* __restrict__ X = use_internal ? g_a : Xext;
    __shared__ float Xs[16][68];     // [k][m] transposed, padded
    __shared__ float Ws[16][128];    // [k][n]

    int tid = threadIdx.x;
    int tx = tid & 31;   // col group: cols tx*4 .. tx*4+3
    int ty = tid >> 5;   // row group: rows ty*8 .. ty*8+7
    int blockRow = blockIdx.x * 64;

    float acc[8][4];
#pragma unroll
    for (int i = 0; i < 8; i++)
#pragma unroll
        for (int j = 0; j < 4; j++) acc[i][j] = 0.f;

    for (int kt = 0; kt < FD; kt += 16) {
        // load X tile (64x16) transposed into Xs
        {
            int r = tid >> 2;          // 0..63
            int cg = tid & 3;          // 0..3
            int row = blockRow + r;
            float4 v = make_float4(0.f, 0.f, 0.f, 0.f);
            if (row < n) v = *(const float4*)&X[row * FD + kt + cg * 4];
            Xs[cg * 4 + 0][r] = v.x;
            Xs[cg * 4 + 1][r] = v.y;
            Xs[cg * 4 + 2][r] = v.z;
            Xs[cg * 4 + 3][r] = v.w;
        }
        // load W tile (16x128)
        {
            int r = tid >> 5;          // 0..7
            int c4 = (tid & 31) * 4;
            *(float4*)&Ws[r][c4]     = *(const float4*)&W[(kt + r) * FD + c4];
            *(float4*)&Ws[r + 8][c4] = *(const float4*)&W[(kt + r + 8) * FD + c4];
        }
        __syncthreads();
#pragma unroll
        for (int kk = 0; kk < 16; kk++) {
            float a[8];
#pragma unroll
            for (int i = 0; i < 8; i++) a[i] = Xs[kk][ty * 8 + i];
            float4 b = *(const float4*)&Ws[kk][tx * 4];
#pragma unroll
            for (int i = 0; i < 8; i++) {
                acc[i][0] += a[i] * b.x;
                acc[i][1] += a[i] * b.y;
                acc[i][2] += a[i] * b.z;
                acc[i][3] += a[i] * b.w;
            }
        }
        __syncthreads();
    }
#pragma unroll
    for (int i = 0; i < 8; i++) {
        int row = blockRow + ty * 8 + i;
        if (row < n) {
            float s = g_dinv[row];
            float4 v = make_float4(acc[i][0] * s, acc[i][1] * s,
                                   acc[i][2] * s, acc[i][3] * s);
            *(float4*)&g_hs[row * FD + tx * 4] = v;
        }
    }
}

// ---------------- Aggregation: out[i] = dinv[i]*(sum_{j in seg(i)} hs[j]) + b
// Segment includes the self-loop entry.  One warp per node; lane owns one
// float4 (512B contiguous row per gather).
__global__ void __launch_bounds__(256) agg_k(const float* __restrict__ bvec,
                                             float* __restrict__ out_ext,
                                             int layer1, int n) {
    int node = blockIdx.x * (blockDim.x >> 5) + (threadIdx.x >> 5);
    if (node >= n) return;
    int lane = threadIdx.x & 31;

    const float4* __restrict__ hs = (const float4*)g_hs;
    float4 acc = make_float4(0.f, 0.f, 0.f, 0.f);
    int beg = g_rowptr[node];
    int end = g_rowptr[node + 1];

    int e = beg;
    for (; e + 3 < end; e += 4) {                // MLP=4 unroll
        int j0 = g_col[e], j1 = g_col[e + 1], j2 = g_col[e + 2], j3 = g_col[e + 3];
        float4 v0 = hs[j0 * 32 + lane];
        float4 v1 = hs[j1 * 32 + lane];
        float4 v2 = hs[j2 * 32 + lane];
        float4 v3 = hs[j3 * 32 + lane];
        acc.x += (v0.x + v1.x) + (v2.x + v3.x);
        acc.y += (v0.y + v1.y) + (v2.y + v3.y);
        acc.z += (v0.z + v1.z) + (v2.z + v3.z);
        acc.w += (v0.w + v1.w) + (v2.w + v3.w);
    }
    for (; e < end; e++) {
        int j = g_col[e];
        float4 v = hs[j * 32 + lane];
        acc.x += v.x; acc.y += v.y; acc.z += v.z; acc.w += v.w;
    }

    float s = g_dinv[node];
    float4 b = ((const float4*)bvec)[lane];
    float4 r;
    r.x = fmaf(acc.x, s, b.x);
    r.y = fmaf(acc.y, s, b.y);
    r.z = fmaf(acc.z, s, b.z);
    r.w = fmaf(acc.w, s, b.w);
    if (layer1) {
        r.x = fmaxf(r.x, 0.f); r.y = fmaxf(r.y, 0.f);
        r.z = fmaxf(r.z, 0.f); r.w = fmaxf(r.w, 0.f);
        ((float4*)g_a)[node * 32 + lane] = r;
    } else {
        ((float4*)out_ext)[node * 32 + lane] = r;
    }
}

// ---------------- launch ----------------
extern "C" void kernel_launch(void* const* d_in, const int* in_sizes, int n_in,
                              void* d_out, int out_size) {
    const float* x  = (const float*)d_in[0];
    const void*  ei = d_in[1];
    const float* W1 = (const float*)d_in[2];
    const float* b1 = (const float*)d_in[3];
    const float* W2 = (const float*)d_in[4];
    const float* b2 = (const float*)d_in[5];

    int n = in_sizes[0] / FD;      // 50000
    int E = in_sizes[1] / 2;       // 800000
    int nbs = (n + 1023) / 1024;

    detect_k<<<1, 256>>>((const int*)ei);
    init_deg_k<<<(n + 255) / 256, 256>>>(n);
    count_k<<<(E + 255) / 256, 256>>>(ei, E);
    scan_local_k<<<nbs, 1024>>>(n);
    scan_block_k<<<1, 1>>>(nbs, n);
    scan_add_k<<<nbs, 1024>>>(n);
    fill_k<<<(E + 255) / 256, 256>>>(ei, E);

    int gemm_blocks = (n + 63) / 64;
    int agg_blocks = (n + 7) / 8;

    gemm_k<<<gemm_blocks, 256>>>(x, W1, 0, n);            // hs = (x@W1)*dinv
    agg_k<<<agg_blocks, 256>>>(b1, (float*)d_out, 1, n);  // g_a = relu(...)
    gemm_k<<<gemm_blocks, 256>>>(nullptr, W2, 1, n);      // hs = (g_a@W2)*dinv
    agg_k<<<agg_blocks, 256>>>(b2, (float*)d_out, 0, n);  // d_out = final
}

// round 6
// speedup vs baseline: 1.0375x; 1.0375x over previous
#include <cuda_runtime.h>
#include <cstdint>

#define NN 50000
#define FD 128
#define EMAXED 1000000

// ---------------- device scratch (no allocations allowed) ----------------
__device__ float g_hs[NN * FD];      // (X@W) * dinv[row]
__device__ float g_a[NN * FD];       // layer-1 activations
__device__ int   g_deg[NN];
__device__ float g_dinv[NN];
__device__ int   g_rowptr[NN + 1];
__device__ int   g_cursor[NN];
__device__ int   g_col[EMAXED];      // CSR (by dst) source indices, self-loop first
__device__ int   g_bsum[256];
__device__ int   g_is64;

// ---------------- detect edge dtype (int64 vs int32) + init degrees --------
// If edges are int64 with values < 50000, every odd 32-bit word is zero.
__global__ void detect_init_k(const int* __restrict__ ei, int n) {
    int i = blockIdx.x * blockDim.x + threadIdx.x;
    if (i < n) g_deg[i] = 1;  // self-loop
    if (blockIdx.x == 0) {
        int w = ei[2 * threadIdx.x + 1];
        int any = __syncthreads_or(w != 0);
        if (threadIdx.x == 0) g_is64 = (any == 0) ? 1 : 0;
    }
}

__global__ void count_k(const void* __restrict__ ei, int E) {
    int e = blockIdx.x * blockDim.x + threadIdx.x;
    if (e >= E) return;
    int dst;
    if (g_is64) dst = (int)((const long long*)ei)[(long long)E + e];
    else        dst = ((const int*)ei)[E + e];
    atomicAdd(&g_deg[dst], 1);
}

// Exclusive scan of g_deg -> g_rowptr.
__global__ void scan_local_k(int n) {
    int i = blockIdx.x * 1024 + threadIdx.x;
    int v = (i < n) ? g_deg[i] : 0;
    int lane = threadIdx.x & 31, wid = threadIdx.x >> 5;
    int x = v;
#pragma unroll
    for (int off = 1; off < 32; off <<= 1) {
        int t = __shfl_up_sync(0xffffffffu, x, off);
        if (lane >= off) x += t;
    }
    __shared__ int wsum[32];
    if (lane == 31) wsum[wid] = x;
    __syncthreads();
    if (wid == 0) {
        int y = wsum[lane];
#pragma unroll
        for (int off = 1; off < 32; off <<= 1) {
            int t = __shfl_up_sync(0xffffffffu, y, off);
            if (lane >= off) y += t;
        }
        wsum[lane] = y;
    }
    __syncthreads();
    int incl = x + (wid > 0 ? wsum[wid - 1] : 0);
    if (i < n) g_rowptr[i] = incl - v;                    // local exclusive
    if (threadIdx.x == 1023) g_bsum[blockIdx.x] = incl;   // block total
}

__global__ void scan_block_k(int nbs, int n) {
    int run = 0;
    for (int b = 0; b < nbs; b++) { int t = g_bsum[b]; g_bsum[b] = run; run += t; }
    g_rowptr[n] = run;
}

__global__ void scan_add_k(int n) {
    int i = blockIdx.x * 1024 + threadIdx.x;
    if (i < n) {
        int p = g_rowptr[i] + g_bsum[blockIdx.x];
        g_rowptr[i] = p;
        g_col[p] = i;            // self-loop occupies the first slot
        g_cursor[i] = p + 1;     // edges fill after it
        g_dinv[i] = rsqrtf((float)g_deg[i]);   // deg >= 1 always
    }
}

__global__ void fill_k(const void* __restrict__ ei, int E) {
    int e = blockIdx.x * blockDim.x + threadIdx.x;
    if (e >= E) return;
    int s, d;
    if (g_is64) {
        const long long* p = (const long long*)ei;
        s = (int)p[e];
        d = (int)p[(long long)E + e];
    } else {
        const int* p = (const int*)ei;
        s = p[e];
        d = p[E + e];
    }
    int pos = atomicAdd(&g_cursor[d], 1);
    g_col[pos] = s;
}

// ---------------- GEMM: out = (X @ W) * dinv[row], out = g_hs ----------------
// BM=64, BN=128, BK=16.  256 threads, thread tile 8 rows x 4 cols.
// Inner loop uses packed fma.rn.f32x2 (2 FMA / fma-pipe issue -> 128 FMA/cyc/SM).
// A operand packs ADJACENT ROWS in the f32x2 lanes so the shared-memory layout
// delivers pairs pre-packed (ulonglong2 broadcast load); B is replicated (b,b).
__global__ void __launch_bounds__(256) gemm_k(const float* __restrict__ Xext,
                                              const float* __restrict__ W,
                                              int use_internal, int n) {
    const float* __restrict__ X = use_internal ? g_a : Xext;
    __shared__ float Xs[16][68];     // [k][m] transposed, padded; rows contiguous
    __shared__ float Ws[16][128];    // [k][n]

    int tid = threadIdx.x;
    int tx = tid & 31;   // col group: cols tx*4 .. tx*4+3
    int ty = tid >> 5;   // row group: rows ty*8 .. ty*8+7
    int blockRow = blockIdx.x * 64;

    // acc[p][c]: f32x2 accumulator, lanes = rows (2p, 2p+1), column tx*4+c
    unsigned long long acc[4][4];
#pragma unroll
    for (int p = 0; p < 4; p++)
#pragma unroll
        for (int c = 0; c < 4; c++) acc[p][c] = 0ull;

    for (int kt = 0; kt < FD; kt += 16) {
        // load X tile (64x16) transposed into Xs
        {
            int r = tid >> 2;          // 0..63
            int cg = tid & 3;          // 0..3
            int row = blockRow + r;
            float4 v = make_float4(0.f, 0.f, 0.f, 0.f);
            if (row < n) v = *(const float4*)&X[row * FD + kt + cg * 4];
            Xs[cg * 4 + 0][r] = v.x;
            Xs[cg * 4 + 1][r] = v.y;
            Xs[cg * 4 + 2][r] = v.z;
            Xs[cg * 4 + 3][r] = v.w;
        }
        // load W tile (16x128)
        {
            int r = tid >> 5;          // 0..7
            int c4 = (tid & 31) * 4;
            *(float4*)&Ws[r][c4]     = *(const float4*)&W[(kt + r) * FD + c4];
            *(float4*)&Ws[r + 8][c4] = *(const float4*)&W[(kt + r + 8) * FD + c4];
        }
        __syncthreads();
#pragma unroll
        for (int kk = 0; kk < 16; kk++) {
            // A: 8 contiguous row values -> 4 packed row-pairs.
            // All lanes in the warp share ty -> broadcast loads.
            // (&Xs[kk][ty*8] is 16B aligned: row stride 272B, offset 32B.)
            const ulonglong2* ap = (const ulonglong2*)&Xs[kk][ty * 8];
            ulonglong2 a01_23 = ap[0];      // rows 0-3 (two packed pairs)
            ulonglong2 a45_67 = ap[1];      // rows 4-7
            unsigned long long apk[4] = {a01_23.x, a01_23.y, a45_67.x, a45_67.y};

            // B: 4 column values, each replicated into both f32x2 lanes.
            float4 bv = *(const float4*)&Ws[kk][tx * 4];
            unsigned long long bpk[4];
            asm("mov.b64 %0, {%1, %1};" : "=l"(bpk[0]) : "f"(bv.x));
            asm("mov.b64 %0, {%1, %1};" : "=l"(bpk[1]) : "f"(bv.y));
            asm("mov.b64 %0, {%1, %1};" : "=l"(bpk[2]) : "f"(bv.z));
            asm("mov.b64 %0, {%1, %1};" : "=l"(bpk[3]) : "f"(bv.w));

#pragma unroll
            for (int p = 0; p < 4; p++)
#pragma unroll
                for (int c = 0; c < 4; c++)
                    asm("fma.rn.f32x2 %0, %1, %2, %0;"
                        : "+l"(acc[p][c]) : "l"(apk[p]), "l"(bpk[c]));
        }
        __syncthreads();
    }

    // Epilogue: unpack row pairs, scale by dinv[row], store float4 per row.
#pragma unroll
    for (int p = 0; p < 4; p++) {
        float2 u0 = *(float2*)&acc[p][0];
        float2 u1 = *(float2*)&acc[p][1];
        float2 u2 = *(float2*)&acc[p][2];
        float2 u3 = *(float2*)&acc[p][3];
        int row0 = blockRow + ty * 8 + 2 * p;
        if (row0 < n) {
            float s = g_dinv[row0];
            *(float4*)&g_hs[row0 * FD + tx * 4] =
                make_float4(u0.x * s, u1.x * s, u2.x * s, u3.x * s);
        }
        int row1 = row0 + 1;
        if (row1 < n) {
            float s = g_dinv[row1];
            *(float4*)&g_hs[row1 * FD + tx * 4] =
                make_float4(u0.y * s, u1.y * s, u2.y * s, u3.y * s);
        }
    }
}

// ---------------- Aggregation: out[i] = dinv[i]*(sum_{j in seg(i)} hs[j]) + b
// Segment includes the self-loop entry.  One warp per node; lane owns one
// float4 (512B contiguous row per gather).
__global__ void __launch_bounds__(256) agg_k(const float* __restrict__ bvec,
                                             float* __restrict__ out_ext,
                                             int layer1, int n) {
    int node = blockIdx.x * (blockDim.x >> 5) + (threadIdx.x >> 5);
    if (node >= n) return;
    int lane = threadIdx.x & 31;

    const float4* __restrict__ hs = (const float4*)g_hs;
    float4 acc = make_float4(0.f, 0.f, 0.f, 0.f);
    int beg = g_rowptr[node];
    int end = g_rowptr[node + 1];

    int e = beg;
    for (; e + 3 < end; e += 4) {                // MLP=4 unroll
        int j0 = g_col[e], j1 = g_col[e + 1], j2 = g_col[e + 2], j3 = g_col[e + 3];
        float4 v0 = hs[j0 * 32 + lane];
        float4 v1 = hs[j1 * 32 + lane];
        float4 v2 = hs[j2 * 32 + lane];
        float4 v3 = hs[j3 * 32 + lane];
        acc.x += (v0.x + v1.x) + (v2.x + v3.x);
        acc.y += (v0.y + v1.y) + (v2.y + v3.y);
        acc.z += (v0.z + v1.z) + (v2.z + v3.z);
        acc.w += (v0.w + v1.w) + (v2.w + v3.w);
    }
    for (; e < end; e++) {
        int j = g_col[e];
        float4 v = hs[j * 32 + lane];
        acc.x += v.x; acc.y += v.y; acc.z += v.z; acc.w += v.w;
    }

    float s = g_dinv[node];
    float4 b = ((const float4*)bvec)[lane];
    float4 r;
    r.x = fmaf(acc.x, s, b.x);
    r.y = fmaf(acc.y, s, b.y);
    r.z = fmaf(acc.z, s, b.z);
    r.w = fmaf(acc.w, s, b.w);
    if (layer1) {
        r.x = fmaxf(r.x, 0.f); r.y = fmaxf(r.y, 0.f);
        r.z = fmaxf(r.z, 0.f); r.w = fmaxf(r.w, 0.f);
        ((float4*)g_a)[node * 32 + lane] = r;
    } else {
        ((float4*)out_ext)[node * 32 + lane] = r;
    }
}

// ---------------- launch ----------------
extern "C" void kernel_launch(void* const* d_in, const int* in_sizes, int n_in,
                              void* d_out, int out_size) {
    const float* x  = (const float*)d_in[0];
    const void*  ei = d_in[1];
    const float* W1 = (const float*)d_in[2];
    const float* b1 = (const float*)d_in[3];
    const float* W2 = (const float*)d_in[4];
    const float* b2 = (const float*)d_in[5];

    int n = in_sizes[0] / FD;      // 50000
    int E = in_sizes[1] / 2;       // 800000
    int nbs = (n + 1023) / 1024;

    detect_init_k<<<(n + 1023) / 1024, 1024>>>((const int*)ei, n);
    count_k<<<(E + 255) / 256, 256>>>(ei, E);
    scan_local_k<<<nbs, 1024>>>(n);
    scan_block_k<<<1, 1>>>(nbs, n);
    scan_add_k<<<nbs, 1024>>>(n);
    fill_k<<<(E + 255) / 256, 256>>>(ei, E);

    int gemm_blocks = (n + 63) / 64;
    int agg_blocks = (n + 7) / 8;

    gemm_k<<<gemm_blocks, 256>>>(x, W1, 0, n);            // hs = (x@W1)*dinv
    agg_k<<<agg_blocks, 256>>>(b1, (float*)d_out, 1, n);  // g_a = relu(...)
    gemm_k<<<gemm_blocks, 256>>>(nullptr, W2, 1, n);      // hs = (g_a@W2)*dinv
    agg_k<<<agg_blocks, 256>>>(b2, (float*)d_out, 0, n);  // d_out = final
}